// round 16
// baseline (speedup 1.0000x reference)
#include <cuda_runtime.h>

#define NCHUNKS 32
#define CHUNK_STRIDE 512          // fixed meta region per chunk (atoms)
#define ROWS    64
#define THREADS 1024
#define XPAD    257               // smem row stride in floats (conflict-free)

// Padded per-atom metadata in 32 FIXED regions of CHUNK_STRIDE slots.
// Every clause padded to a multiple of 4 atoms; chunk tail padded to mult 8.
// Flush only on atom3 of a 4-atom group (bit31 of .z; .w = gate*leaf).
// Identity pad atoms: {0,-1000,0,0} -> e underflows -> clamp -> p unchanged.
// arg = A'*x[fid] + B' ; e = exp2(arg) ; clause = 1/prod(1+e)
__device__ float4 g_meta[NCHUNKS * CHUNK_STRIDE + 16];  // +16 overread slack
__device__ int    g_chunk_len[NCHUNKS];       // padded length (mult of 8)
__device__ float  g_empty[NCHUNKS];           // sum g over EMPTY clauses

__device__ __forceinline__ float ex2a(float a) {
    float r; asm("ex2.approx.f32 %0, %1;" : "=f"(r) : "f"(a)); return r;
}
__device__ __forceinline__ float rcpa(float a) {
    float r; asm("rcp.approx.f32 %0, %1;" : "=f"(r) : "f"(a)); return r;
}

// ONE setup kernel: block k owns chunk k (clauses [k*cpc,(k+1)*cpc), cpc<=32).
// Phase 1: all threads scan cids, keep own-chunk clause boundaries in smem.
// Phase 2: warp 0 builds tables (shfl scan) + pads into the fixed region.
// Phase 3: all threads scatter the chunk's atoms.
__global__ void cln_setup(const float* __restrict__ w,
                          const float* __restrict__ eta,
                          const float* __restrict__ leaf,
                          const float* __restrict__ gate,
                          const int* __restrict__ fid,
                          const int* __restrict__ csgn,
                          const int* __restrict__ cids,
                          int n_atoms, int n_clauses, int cpc) {
    __shared__ int   s_src[32], s_last[32], s_dst[32], s_plen[32];
    __shared__ float s_g[32];
    __shared__ int   s_lo, s_hi;

    const int k     = blockIdx.x;
    const int tid   = threadIdx.x;
    const int cbase = k * cpc;
    const int cend  = cbase + cpc;
    const float L2E = 1.4426950408889634f;

    if (tid < cpc) { s_src[tid] = -1; s_last[tid] = -1; }
    __syncthreads();

    // Phase 1: full scan, coalesced; record boundaries of own clauses only.
    for (int i = tid; i < n_atoms; i += blockDim.x) {
        int c  = cids[i];
        int cn = (i + 1 < n_atoms) ? cids[i + 1] : 0x7fffffff;
        if (i == 0 && c >= cbase && c < cend) s_src[c - cbase] = 0;
        if (cn != c) {
            if (c  >= cbase && c  < cend) s_last[c - cbase] = i;
            if (cn >= cbase && cn < cend) s_src[cn - cbase] = i + 1;
        }
    }
    __syncthreads();

    // Phase 2: warp 0 — tables, scan, pads.
    if (tid < 32) {
        const bool valid = (tid < cpc) && (cbase + tid < n_clauses);
        int len = 0, plen = 0;
        float g = 0.f;
        if (valid) {
            g = gate[cbase + tid] * leaf[cbase + tid];
            if (s_src[tid] >= 0) {
                len  = s_last[tid] - s_src[tid] + 1;
                plen = (len + 3) & ~3;
            }
        }
        // empty-clause sum for this chunk
        float es = (valid && len == 0) ? g : 0.f;
        #pragma unroll
        for (int d = 16; d; d >>= 1) es += __shfl_xor_sync(0xffffffff, es, d);
        if (tid == 0) g_empty[k] = es;

        // exclusive scan of plen
        int x = plen;
        #pragma unroll
        for (int d = 1; d < 32; d <<= 1) {
            int v = __shfl_up_sync(0xffffffff, x, d);
            if (tid >= d) x += v;
        }
        int clen = __shfl_sync(0xffffffff, x, 31);    // chunk len (mult of 4)
        int dst  = k * CHUNK_STRIDE + (x - plen);

        if (valid) {
            s_dst[tid]  = dst;
            s_plen[tid] = plen;
            s_g[tid]    = g;
            for (int j = len; j < plen; ++j) {        // <=3 identity pads
                int fz = 0; float gg = 0.f;
                if (j == plen - 1) { fz = 0x80000000; gg = g; }
                g_meta[dst + j] = make_float4(0.f, -1000.f,
                                              __int_as_float(fz), gg);
            }
        }
        int ctp = (clen + 7) & ~7;                    // pad chunk to mult 8
        if (tid < 8 && clen + tid < ctp)
            g_meta[k * CHUNK_STRIDE + clen + tid] =
                make_float4(0.f, -1000.f, 0.f, 0.f);
        if (tid == 0) g_chunk_len[k] = ctp;

        // chunk atom range for phase 3
        int lov = (valid && s_src[tid] >= 0) ? s_src[tid]  : 0x7fffffff;
        int hiv = (valid && s_src[tid] >= 0) ? s_last[tid] : -1;
        #pragma unroll
        for (int d = 16; d; d >>= 1) {
            lov = min(lov, __shfl_xor_sync(0xffffffff, lov, d));
            hiv = max(hiv, __shfl_xor_sync(0xffffffff, hiv, d));
        }
        if (tid == 0) { s_lo = lov; s_hi = hiv; }
    }
    __syncthreads();

    // Phase 3: scatter this chunk's atoms (coalesced inputs, smem tables).
    if (s_hi >= 0) {
        for (int i = s_lo + tid; i <= s_hi; i += blockDim.x) {
            int c = cids[i] - cbase;                  // in [0, cpc)
            int j = i - s_src[c];
            float sB = (csgn[i] == 0) ? -100.0f : 100.0f; // sign * B_CONST
            float A2 = -sB * w[i] * L2E;
            float B2 = -sB * (0.01f - eta[i]) * L2E;      // EPS = 0.01
            int fz = fid[i];
            float gg = 0.f;
            if (j == s_plen[c] - 1) { fz |= 0x80000000; gg = s_g[c]; }
            g_meta[s_dst[c] + j] = make_float4(A2, B2, __int_as_float(fz), gg);
        }
    }
}

__global__ __launch_bounds__(THREADS, 1)
void cln_main(const float* __restrict__ x, float* __restrict__ y, int nfeat) {
    extern __shared__ float xs[];            // ROWS * XPAD floats
    __shared__ float ys[ROWS];

    const int rowBase = blockIdx.x * ROWS;

    // Stage 64 rows of x into shared (coalesced float4 loads)
    const int n4f = nfeat >> 2;
    for (int i = threadIdx.x; i < ROWS * n4f; i += THREADS) {
        int row = i / n4f, f4 = i - row * n4f;
        float4 v = reinterpret_cast<const float4*>(
                       x + (size_t)(rowBase + row) * nfeat)[f4];
        float* d = xs + row * XPAD + (f4 << 2);
        d[0] = v.x; d[1] = v.y; d[2] = v.z; d[3] = v.w;
    }
    if (threadIdx.x < ROWS) ys[threadIdx.x] = 0.f;
    __syncthreads();

    const int chunk = threadIdx.x >> 5;      // warp == chunk
    const int lane  = threadIdx.x & 31;

    const float* xr0 = xs + lane * XPAD;     // lane owns rows lane and lane+32
    const float ec = g_empty[chunk];
    float y0 = ec, y1 = ec;
    float p0 = 1.f, p1 = 1.f;

    const float4* __restrict__ mp = g_meta + chunk * CHUNK_STRIDE;
    const int n = g_chunk_len[chunk];        // mult of 8

    // CLAMP IS LOAD-BEARING: e can be inf (fma(p,inf,p)=inf), and a later
    // e==0 would give fma(inf,0,inf)=NaN. Clamping e>=1e-37 makes the inf
    // path stable (inf*tiny=inf), and rcp(inf)=0 matches reference underflow.
#define EVAL(mm, f, off) fmaxf(ex2a(fmaf((mm).x, xr0[(f) + (off)], (mm).y)), 1e-37f)

    // Flush only possible at atom3 of a group: no per-atom flags/SELs.
#define PROCESS(m0, m1, m2, m3)                                        \
    {                                                                  \
        int f0 = __float_as_int((m0).z);                               \
        int f1 = __float_as_int((m1).z);                               \
        int f2 = __float_as_int((m2).z);                               \
        int fz3 = __float_as_int((m3).z);                              \
        int f3 = fz3 & 0x7fffffff;                                     \
        float e00 = EVAL(m0, f0, 0),         e01 = EVAL(m1, f1, 0);    \
        float e02 = EVAL(m2, f2, 0),         e03 = EVAL(m3, f3, 0);    \
        float e10 = EVAL(m0, f0, 32 * XPAD), e11 = EVAL(m1, f1, 32 * XPAD); \
        float e12 = EVAL(m2, f2, 32 * XPAD), e13 = EVAL(m3, f3, 32 * XPAD); \
        p0 = fmaf(p0, e00, p0); p0 = fmaf(p0, e01, p0);                \
        p0 = fmaf(p0, e02, p0); p0 = fmaf(p0, e03, p0);                \
        p1 = fmaf(p1, e10, p1); p1 = fmaf(p1, e11, p1);                \
        p1 = fmaf(p1, e12, p1); p1 = fmaf(p1, e13, p1);                \
        if (fz3 < 0) {                                                 \
            y0 = fmaf((m3).w, rcpa(p0), y0);                           \
            y1 = fmaf((m3).w, rcpa(p1), y1);                           \
            p0 = 1.f; p1 = 1.f;                                        \
        }                                                              \
    }

    if (n > 0) {
        // 2-group double-buffered software pipeline; no register copies.
        float4 a0 = mp[0], a1 = mp[1], a2 = mp[2], a3 = mp[3];
        for (int i = 0; i < n; i += 8) {
            float4 b0 = mp[i + 4], b1 = mp[i + 5];
            float4 b2 = mp[i + 6], b3 = mp[i + 7];
            PROCESS(a0, a1, a2, a3);
            a0 = mp[i + 8];  a1 = mp[i + 9];     // overread stays inside the
            a2 = mp[i + 10]; a3 = mp[i + 11];    // slack-padded g_meta
            PROCESS(b0, b1, b2, b3);
        }
    }

    atomicAdd(&ys[lane], y0);
    atomicAdd(&ys[lane + 32], y1);
    __syncthreads();
    if (threadIdx.x < ROWS)
        y[rowBase + threadIdx.x] = ys[threadIdx.x];
}

extern "C" void kernel_launch(void* const* d_in, const int* in_sizes, int n_in,
                              void* d_out, int out_size) {
    const float* x    = (const float*)d_in[0];
    const float* w    = (const float*)d_in[1];
    const float* eta  = (const float*)d_in[2];
    const float* leaf = (const float*)d_in[3];
    const float* gate = (const float*)d_in[4];
    const int*   fid  = (const int*)d_in[5];
    const int*   csgn = (const int*)d_in[6];
    const int*   cids = (const int*)d_in[7];

    const int n_atoms   = in_sizes[1];
    const int n_clauses = in_sizes[3];
    const int batch     = out_size;
    const int nfeat     = in_sizes[0] / batch;
    const int cpc       = n_clauses / NCHUNKS;   // must be <= 32

    cln_setup<<<NCHUNKS, 256>>>(w, eta, leaf, gate, fid, csgn, cids,
                                n_atoms, n_clauses, cpc);

    size_t smem = (size_t)ROWS * XPAD * sizeof(float);
    cudaFuncSetAttribute(cln_main, cudaFuncAttributeMaxDynamicSharedMemorySize,
                         (int)smem);
    cln_main<<<batch / ROWS, THREADS, smem>>>(x, (float*)d_out, nfeat);
}

// round 17
// speedup vs baseline: 1.0790x; 1.0790x over previous
#include <cuda_runtime.h>

#define NCHUNKS 32
#define CHUNK_STRIDE 512          // fixed meta region per chunk (atoms)
#define ROWS    64
#define THREADS 1024
#define XPAD    257               // smem row stride in floats (conflict-free)

// Padded per-atom metadata in 32 FIXED regions of CHUNK_STRIDE slots.
// Every clause padded to a multiple of 4 atoms; chunk tail padded to mult 8.
// Flush only on atom3 of a 4-atom group (bit31 of .z; .w = gate*leaf).
// Identity pad atoms: {0,-1000,0,0} -> e underflows -> clamp -> p unchanged.
// arg = A'*x[fid] + B' ; e = exp2(arg) ; clause = 1/prod(1+e)
__device__ float4 g_meta[NCHUNKS * CHUNK_STRIDE + 16];  // +16 overread slack
__device__ int    g_chunk_len[NCHUNKS];       // padded length (mult of 8)
__device__ float  g_empty[NCHUNKS];           // sum g over EMPTY clauses

__device__ __forceinline__ float ex2a(float a) {
    float r; asm("ex2.approx.f32 %0, %1;" : "=f"(r) : "f"(a)); return r;
}
__device__ __forceinline__ float rcpa(float a) {
    float r; asm("rcp.approx.f32 %0, %1;" : "=f"(r) : "f"(a)); return r;
}

// ONE setup kernel, 32 blocks x 1024 threads. Block k owns chunk k.
// Phase 1: boundary scan with PREFETCHED loads (all LDGs batched before the
//          branchy processing -> one latency exposure, not 16).
// Phase 2: warp 0 builds tables (shfl scan) + pads into the fixed region.
// Phase 3: scatter the chunk's atoms (single iteration at 1024 threads).
__global__ __launch_bounds__(THREADS)
void cln_setup(const float* __restrict__ w,
               const float* __restrict__ eta,
               const float* __restrict__ leaf,
               const float* __restrict__ gate,
               const int* __restrict__ fid,
               const int* __restrict__ csgn,
               const int* __restrict__ cids,
               int n_atoms, int n_clauses, int cpc) {
    __shared__ int   s_src[32], s_last[32], s_dst[32], s_plen[32];
    __shared__ float s_g[32];
    __shared__ int   s_lo, s_hi;

    const int k     = blockIdx.x;
    const int tid   = threadIdx.x;
    const int cbase = k * cpc;
    const int cend  = cbase + cpc;
    const float L2E = 1.4426950408889634f;

    if (tid < cpc) { s_src[tid] = -1; s_last[tid] = -1; }
    __syncthreads();

    // Phase 1: prefetch ALL (c, cn) pairs first (high MLP), then process.
    {
        const int NIT = (n_atoms + THREADS - 1) / THREADS;  // typ. 4
        int pc[8], pn[8];                                    // NIT <= 8
        #pragma unroll
        for (int j = 0; j < 8; ++j) {
            if (j < NIT) {
                int i = tid + j * THREADS;
                pc[j] = (i < n_atoms)     ? cids[i]     : 0x7fffffff;
                pn[j] = (i + 1 < n_atoms) ? cids[i + 1] : 0x7fffffff;
            }
        }
        #pragma unroll
        for (int j = 0; j < 8; ++j) {
            if (j < NIT) {
                int i = tid + j * THREADS;
                if (i < n_atoms) {
                    int c = pc[j], cn = pn[j];
                    if (i == 0 && c >= cbase && c < cend)
                        s_src[c - cbase] = 0;
                    if (cn != c) {
                        if (c  >= cbase && c  < cend) s_last[c - cbase] = i;
                        if (cn >= cbase && cn < cend) s_src[cn - cbase] = i + 1;
                    }
                }
            }
        }
    }
    __syncthreads();

    // Phase 2: warp 0 — tables, scan, pads.
    if (tid < 32) {
        const bool valid = (tid < cpc) && (cbase + tid < n_clauses);
        int len = 0, plen = 0;
        float g = 0.f;
        if (valid) {
            g = gate[cbase + tid] * leaf[cbase + tid];
            if (s_src[tid] >= 0) {
                len  = s_last[tid] - s_src[tid] + 1;
                plen = (len + 3) & ~3;
            }
        }
        // empty-clause sum for this chunk
        float es = (valid && len == 0) ? g : 0.f;
        #pragma unroll
        for (int d = 16; d; d >>= 1) es += __shfl_xor_sync(0xffffffff, es, d);
        if (tid == 0) g_empty[k] = es;

        // exclusive scan of plen
        int x = plen;
        #pragma unroll
        for (int d = 1; d < 32; d <<= 1) {
            int v = __shfl_up_sync(0xffffffff, x, d);
            if (tid >= d) x += v;
        }
        int clen = __shfl_sync(0xffffffff, x, 31);    // chunk len (mult of 4)
        int dst  = k * CHUNK_STRIDE + (x - plen);

        if (valid) {
            s_dst[tid]  = dst;
            s_plen[tid] = plen;
            s_g[tid]    = g;
            for (int j = len; j < plen; ++j) {        // <=3 identity pads
                int fz = 0; float gg = 0.f;
                if (j == plen - 1) { fz = 0x80000000; gg = g; }
                g_meta[dst + j] = make_float4(0.f, -1000.f,
                                              __int_as_float(fz), gg);
            }
        }
        int ctp = (clen + 7) & ~7;                    // pad chunk to mult 8
        if (tid < 8 && clen + tid < ctp)
            g_meta[k * CHUNK_STRIDE + clen + tid] =
                make_float4(0.f, -1000.f, 0.f, 0.f);
        if (tid == 0) g_chunk_len[k] = ctp;

        // chunk atom range for phase 3
        int lov = (valid && s_src[tid] >= 0) ? s_src[tid]  : 0x7fffffff;
        int hiv = (valid && s_src[tid] >= 0) ? s_last[tid] : -1;
        #pragma unroll
        for (int d = 16; d; d >>= 1) {
            lov = min(lov, __shfl_xor_sync(0xffffffff, lov, d));
            hiv = max(hiv, __shfl_xor_sync(0xffffffff, hiv, d));
        }
        if (tid == 0) { s_lo = lov; s_hi = hiv; }
    }
    __syncthreads();

    // Phase 3: scatter this chunk's atoms (typically ONE iteration @1024 thr).
    if (s_hi >= 0) {
        for (int i = s_lo + tid; i <= s_hi; i += THREADS) {
            int c = cids[i] - cbase;                  // in [0, cpc)
            int j = i - s_src[c];
            float sB = (csgn[i] == 0) ? -100.0f : 100.0f; // sign * B_CONST
            float A2 = -sB * w[i] * L2E;
            float B2 = -sB * (0.01f - eta[i]) * L2E;      // EPS = 0.01
            int fz = fid[i];
            float gg = 0.f;
            if (j == s_plen[c] - 1) { fz |= 0x80000000; gg = s_g[c]; }
            g_meta[s_dst[c] + j] = make_float4(A2, B2, __int_as_float(fz), gg);
        }
    }
}

__global__ __launch_bounds__(THREADS, 1)
void cln_main(const float* __restrict__ x, float* __restrict__ y, int nfeat) {
    extern __shared__ float xs[];            // ROWS * XPAD floats
    __shared__ float ys[ROWS];

    const int rowBase = blockIdx.x * ROWS;

    // Stage 64 rows of x into shared (coalesced float4 loads)
    const int n4f = nfeat >> 2;
    for (int i = threadIdx.x; i < ROWS * n4f; i += THREADS) {
        int row = i / n4f, f4 = i - row * n4f;
        float4 v = reinterpret_cast<const float4*>(
                       x + (size_t)(rowBase + row) * nfeat)[f4];
        float* d = xs + row * XPAD + (f4 << 2);
        d[0] = v.x; d[1] = v.y; d[2] = v.z; d[3] = v.w;
    }
    if (threadIdx.x < ROWS) ys[threadIdx.x] = 0.f;
    __syncthreads();

    const int chunk = threadIdx.x >> 5;      // warp == chunk
    const int lane  = threadIdx.x & 31;

    const float* xr0 = xs + lane * XPAD;     // lane owns rows lane and lane+32
    const float ec = g_empty[chunk];
    float y0 = ec, y1 = ec;
    float p0 = 1.f, p1 = 1.f;

    const float4* __restrict__ mp = g_meta + chunk * CHUNK_STRIDE;
    const int n = g_chunk_len[chunk];        // mult of 8

    // CLAMP IS LOAD-BEARING: e can be inf (fma(p,inf,p)=inf), and a later
    // e==0 would give fma(inf,0,inf)=NaN. Clamping e>=1e-37 makes the inf
    // path stable (inf*tiny=inf), and rcp(inf)=0 matches reference underflow.
#define EVAL(mm, f, off) fmaxf(ex2a(fmaf((mm).x, xr0[(f) + (off)], (mm).y)), 1e-37f)

    // Flush only possible at atom3 of a group: no per-atom flags/SELs.
#define PROCESS(m0, m1, m2, m3)                                        \
    {                                                                  \
        int f0 = __float_as_int((m0).z);                               \
        int f1 = __float_as_int((m1).z);                               \
        int f2 = __float_as_int((m2).z);                               \
        int fz3 = __float_as_int((m3).z);                              \
        int f3 = fz3 & 0x7fffffff;                                     \
        float e00 = EVAL(m0, f0, 0),         e01 = EVAL(m1, f1, 0);    \
        float e02 = EVAL(m2, f2, 0),         e03 = EVAL(m3, f3, 0);    \
        float e10 = EVAL(m0, f0, 32 * XPAD), e11 = EVAL(m1, f1, 32 * XPAD); \
        float e12 = EVAL(m2, f2, 32 * XPAD), e13 = EVAL(m3, f3, 32 * XPAD); \
        p0 = fmaf(p0, e00, p0); p0 = fmaf(p0, e01, p0);                \
        p0 = fmaf(p0, e02, p0); p0 = fmaf(p0, e03, p0);                \
        p1 = fmaf(p1, e10, p1); p1 = fmaf(p1, e11, p1);                \
        p1 = fmaf(p1, e12, p1); p1 = fmaf(p1, e13, p1);                \
        if (fz3 < 0) {                                                 \
            y0 = fmaf((m3).w, rcpa(p0), y0);                           \
            y1 = fmaf((m3).w, rcpa(p1), y1);                           \
            p0 = 1.f; p1 = 1.f;                                        \
        }                                                              \
    }

    if (n > 0) {
        // 2-group double-buffered software pipeline; no register copies.
        float4 a0 = mp[0], a1 = mp[1], a2 = mp[2], a3 = mp[3];
        for (int i = 0; i < n; i += 8) {
            float4 b0 = mp[i + 4], b1 = mp[i + 5];
            float4 b2 = mp[i + 6], b3 = mp[i + 7];
            PROCESS(a0, a1, a2, a3);
            a0 = mp[i + 8];  a1 = mp[i + 9];     // overread stays inside the
            a2 = mp[i + 10]; a3 = mp[i + 11];    // slack-padded g_meta
            PROCESS(b0, b1, b2, b3);
        }
    }

    atomicAdd(&ys[lane], y0);
    atomicAdd(&ys[lane + 32], y1);
    __syncthreads();
    if (threadIdx.x < ROWS)
        y[rowBase + threadIdx.x] = ys[threadIdx.x];
}

extern "C" void kernel_launch(void* const* d_in, const int* in_sizes, int n_in,
                              void* d_out, int out_size) {
    const float* x    = (const float*)d_in[0];
    const float* w    = (const float*)d_in[1];
    const float* eta  = (const float*)d_in[2];
    const float* leaf = (const float*)d_in[3];
    const float* gate = (const float*)d_in[4];
    const int*   fid  = (const int*)d_in[5];
    const int*   csgn = (const int*)d_in[6];
    const int*   cids = (const int*)d_in[7];

    const int n_atoms   = in_sizes[1];
    const int n_clauses = in_sizes[3];
    const int batch     = out_size;
    const int nfeat     = in_sizes[0] / batch;
    const int cpc       = n_clauses / NCHUNKS;   // must be <= 32

    cln_setup<<<NCHUNKS, THREADS>>>(w, eta, leaf, gate, fid, csgn, cids,
                                    n_atoms, n_clauses, cpc);

    size_t smem = (size_t)ROWS * XPAD * sizeof(float);
    cudaFuncSetAttribute(cln_main, cudaFuncAttributeMaxDynamicSharedMemorySize,
                         (int)smem);
    cln_main<<<batch / ROWS, THREADS, smem>>>(x, (float*)d_out, nfeat);
}